// round 17
// baseline (speedup 1.0000x reference)
#include <cuda_runtime.h>
#include <cuda_fp16.h>
#include <math.h>
#include <stdint.h>

#define T_TOK 32768
#define DIM   128
#define KC    8192
#define BM    128
#define NT    64
#define ITERS (KC / NT)          /* 128 */
#define GRID_GEMM (T_TOK / BM)   /* 256 */
#define TILE_BYTES 16384
#define SMEM_GEMM (3 * TILE_BYTES)   /* 48KB: 3-deep ring */
#define PAD 132
#define SMEM_PROJ (2 * 128 * PAD * 4)

/* ---------------- device scratch (no allocations) ---------------- */
__device__ __align__(16) unsigned char g_cbt[ITERS * TILE_BYTES]; /* 2MB fp16 B frags */
__device__ float  g_codebook[KC * DIM];
__device__ __align__(16) float  g_cnorm[KC];
__device__ __align__(16) __half g_cnh[KC];    /* fp16 cnorm for screening */
__device__ int    g_counts[KC];
__device__ double g_ssep[GRID_GEMM];
__device__ unsigned int g_done;

__device__ __forceinline__ uint32_t smem_u32(const void* p) {
    uint32_t a;
    asm("{ .reg .u64 t; cvta.to.shared.u64 t, %1; cvt.u32.u64 %0, t; }"
        : "=r"(a) : "l"(p));
    return a;
}

#define CP16(dst, src) \
    asm volatile("cp.async.cg.shared.global [%0], [%1], 16;" :: "r"((uint32_t)(dst)), "l"(src))
#define CP_COMMIT() asm volatile("cp.async.commit_group;" ::: "memory")
#define CP_WAIT1()  asm volatile("cp.async.wait_group 1;"  ::: "memory")
#define CP_WAIT0()  asm volatile("cp.async.wait_group 0;"  ::: "memory")

/* fp16-accumulator HMMA: D,C are 2 x f16x2 regs */
#define MMA_F16ACC(d, a, b0, b1) \
    asm volatile("mma.sync.aligned.m16n8k16.row.col.f16.f16.f16.f16 " \
                 "{%0,%1}, {%2,%3,%4,%5}, {%6,%7}, {%0,%1};" \
                 : "+r"((d)[0]), "+r"((d)[1]) \
                 : "r"((a)[0]), "r"((a)[1]), "r"((a)[2]), "r"((a)[3]), \
                   "r"(b0), "r"(b1))

#define INS2(tv0, tv1, ti0, ti1, v, n) do {                                   \
    if ((v) < (tv1)) {                                                        \
        if ((v) < (tv0)) { tv1 = tv0; ti1 = ti0; tv0 = (v); ti0 = (n); }      \
        else             { tv1 = (v); ti1 = (n); }                            \
    }                                                                         \
} while (0)

/* ---------------- projection GEMM: C = emb @ W^T + b (128 codes/block) ----------------
   Emits fp32 codebook, cnorm (fp32 + fp16), fp16 packed B fragments; zeroes counts/done.
   Packed layout per 64-code tile (16KB): [nblk(8)][kblk(8)][lane(32)] x 8B,
   8B = {h(k), h(k+1), h(k+8), h(k+9)}, lane = nl*4 + ksub,
   n = tile*64 + nblk*8 + nl, k = kblk*16 + regsel*8 + ksub*2 + par */
__global__ __launch_bounds__(256, 1)
void k_proj(const float* __restrict__ emb,
            const float* __restrict__ pw,
            const float* __restrict__ pbias) {
    extern __shared__ float ps[];
    float* es = ps;
    float* wsm = ps + 128 * PAD;
    const int tid = threadIdx.x;
    const int tx = tid & 15, ty = tid >> 4;
    const int c0 = blockIdx.x * 128;

    if (tid < 128) g_counts[c0 + tid] = 0;
    if (blockIdx.x == 0 && tid == 0) g_done = 0;

#pragma unroll
    for (int i = 0; i < 16; i++) {
        int f = tid + i * 256;
        int row = f >> 5;
        int c4 = f & 31;
        int sw = (((row >> 2) ^ (c4 & 7)) << 2) | (row & 3);
        float4 v = *((const float4*)(emb + (size_t)(c0 + row) * DIM) + c4);
        es[(4 * c4 + 0) * PAD + sw] = v.x;
        es[(4 * c4 + 1) * PAD + sw] = v.y;
        es[(4 * c4 + 2) * PAD + sw] = v.z;
        es[(4 * c4 + 3) * PAD + sw] = v.w;
        float4 w = *((const float4*)(pw + (size_t)row * DIM) + c4);
        wsm[(4 * c4 + 0) * PAD + sw] = w.x;
        wsm[(4 * c4 + 1) * PAD + sw] = w.y;
        wsm[(4 * c4 + 2) * PAD + sw] = w.z;
        wsm[(4 * c4 + 3) * PAD + sw] = w.w;
    }
    __syncthreads();

    float acc[8][8];
#pragma unroll
    for (int im = 0; im < 8; im++)
#pragma unroll
        for (int jn = 0; jn < 8; jn++) acc[im][jn] = 0.0f;

#pragma unroll 4
    for (int k = 0; k < 128; k++) {
        int s = (k >> 2) & 7;
        const float* er = es + k * PAD;
        const float* wr = wsm + k * PAD;
        float4 a0 = *(const float4*)(er + ((ty ^ s) << 2));
        float4 a1 = *(const float4*)(er + 64 + ((ty ^ s) << 2));
        float4 b0 = *(const float4*)(wr + ((tx ^ s) << 2));
        float4 b1 = *(const float4*)(wr + 64 + ((tx ^ s) << 2));
        float a[8] = {a0.x, a0.y, a0.z, a0.w, a1.x, a1.y, a1.z, a1.w};
        float b[8] = {b0.x, b0.y, b0.z, b0.w, b1.x, b1.y, b1.z, b1.w};
#pragma unroll
        for (int im = 0; im < 8; im++)
#pragma unroll
            for (int jn = 0; jn < 8; jn++)
                acc[im][jn] = fmaf(a[im], b[jn], acc[im][jn]);
    }

    float cnp[8];
#pragma unroll
    for (int im = 0; im < 8; im++) cnp[im] = 0.0f;

#pragma unroll
    for (int im = 0; im < 8; im++) {
        int cl = (im < 4) ? (ty * 4 + im) : (64 + ty * 4 + im - 4);
        int cg = c0 + cl;
        int tile = cg >> 6, nblk = (cg >> 3) & 7, nl = cg & 7;
#pragma unroll
        for (int jn = 0; jn < 8; jn++) {
            int d = (jn < 4) ? (tx * 4 + jn) : (64 + tx * 4 + jn - 4);
            float val = acc[im][jn] + pbias[d];
            g_codebook[(size_t)cg * DIM + d] = val;
            cnp[im] = fmaf(val, val, cnp[im]);
            int kblk = d >> 4, kin = d & 15;
            int regsel = kin >> 3, ksub = (kin & 7) >> 1, par = kin & 1;
            int lane = nl * 4 + ksub;
            size_t off = (size_t)tile * TILE_BYTES + nblk * 2048 + kblk * 256
                       + lane * 8 + regsel * 4 + par * 2;
            *(__half*)(g_cbt + off) = __float2half_rn(val);
        }
    }
#pragma unroll
    for (int im = 0; im < 8; im++) {
#pragma unroll
        for (int o = 8; o > 0; o >>= 1)
            cnp[im] += __shfl_xor_sync(0xffffffffu, cnp[im], o, 16);
    }
    if (tx == 0) {
#pragma unroll
        for (int im = 0; im < 8; im++) {
            int cl = (im < 4) ? (ty * 4 + im) : (64 + ty * 4 + im - 4);
            g_cnorm[c0 + cl] = cnp[im];
            g_cnh[c0 + cl] = __float2half_rn(cnp[im]);
        }
    }
}

/* ---------------- fused: fp16-acc HMMA GEMM + screened per-lane top-2 + rescore + loss ---------------- */
__global__ __launch_bounds__(256, 2)
void k_gemm(const float* __restrict__ z, float* __restrict__ out) {
    extern __shared__ unsigned char smem[];
    const uint32_t sb = smem_u32(smem);
    const int tid = threadIdx.x;
    const int lane = tid & 31;
    const int warp = tid >> 5;
    const int r = lane >> 2;
    const int cc = lane & 3;
    const int m0 = blockIdx.x * BM;

    /* prologue: prefetch B tiles 0 and 1 into ring slots 0,1 */
#pragma unroll
    for (int t = 0; t < 2; t++) {
        const unsigned char* src = g_cbt + (size_t)t * TILE_BYTES;
        uint32_t dst = sb + t * TILE_BYTES;
#pragma unroll
        for (int j = 0; j < 4; j++) {
            uint32_t off = (uint32_t)(tid + j * 256) * 16;
            CP16(dst + off, src + off);
        }
        CP_COMMIT();
    }

    /* A fragments (fp16) in registers */
    uint32_t A[8][4];
    {
        const float* z0 = z + (size_t)(m0 + warp * 16 + r) * DIM;
#pragma unroll
        for (int kb = 0; kb < 8; kb++) {
#pragma unroll
            for (int q = 0; q < 4; q++) {
                const float* src = z0 + ((q & 1) ? 8 * DIM : 0) + kb * 16 + (q >> 1) * 8 + cc * 2;
                float2 v = *(const float2*)src;
                __half2 hh = __floats2half2_rn(v.x, v.y);
                A[kb][q] = *(uint32_t*)&hh;
            }
        }
    }

    /* per-lane top-2 (fp32 exact values) + fp16 screening thresholds */
    float av0 = 3.4e38f, av1 = 3.4e38f, bv0 = 3.4e38f, bv1 = 3.4e38f;
    int ai0 = 0, ai1 = 0, bi0 = 0, bi1 = 0;
    __half2 thrA = __floats2half2_rn(60000.0f, 60000.0f);
    __half2 thrB = thrA;
    const __half2 neg2 = __floats2half2_rn(-2.0f, -2.0f);

    int buf = 0, nbuf = 2;
    for (int i = 0; i < ITERS; i++) {
        CP_WAIT1();
        __syncthreads();
        if (i + 2 < ITERS) {
            const unsigned char* src = g_cbt + (size_t)(i + 2) * TILE_BYTES;
            uint32_t dst = sb + nbuf * TILE_BYTES;
#pragma unroll
            for (int j = 0; j < 4; j++) {
                uint32_t off = (uint32_t)(tid + j * 256) * 16;
                CP16(dst + off, src + off);
            }
        }
        CP_COMMIT();

        uint32_t acc[8][2];
#pragma unroll
        for (int nb = 0; nb < 8; nb++) { acc[nb][0] = 0u; acc[nb][1] = 0u; }

        const uint32_t bbase = sb + buf * TILE_BYTES + lane * 8;
#pragma unroll
        for (int kb = 0; kb < 8; kb++) {
#pragma unroll
            for (int nb = 0; nb < 8; nb++) {
                uint32_t b0, b1;
                asm volatile("ld.shared.v2.b32 {%0,%1},[%2];"
                             : "=r"(b0), "=r"(b1) : "r"(bbase + nb * 2048 + kb * 256));
                MMA_F16ACC(acc[nb], A[kb], b0, b1);
            }
        }

        const int n0i = i * 64;
#pragma unroll
        for (int nb = 0; nb < 8; nb++) {
            int n = n0i + nb * 8 + cc * 2;
            __half2 cn2 = *(const __half2*)(g_cnh + n);
            __half2 sA = __hfma2(*(__half2*)&acc[nb][0], neg2, cn2);
            __half2 sB = __hfma2(*(__half2*)&acc[nb][1], neg2, cn2);
            __half2 mA = __hlt2(sA, thrA);
            __half2 mB = __hlt2(sB, thrB);
            if (*(uint32_t*)&mA) {   /* rare slow path: exact insert, row a */
                float2 cnf = *(const float2*)(g_cnorm + n);
                float2 fa = __half22float2(*(__half2*)&acc[nb][0]);
                float s0 = fmaf(-2.0f, fa.x, cnf.x);
                float s1 = fmaf(-2.0f, fa.y, cnf.y);
                INS2(av0, av1, ai0, ai1, s0, n);
                INS2(av0, av1, ai0, ai1, s1, n + 1);
                thrA = __half2half2(__float2half_rn(av1));
            }
            if (*(uint32_t*)&mB) {   /* rare slow path: exact insert, row b */
                float2 cnf = *(const float2*)(g_cnorm + n);
                float2 fb = __half22float2(*(__half2*)&acc[nb][1]);
                float s2 = fmaf(-2.0f, fb.x, cnf.x);
                float s3 = fmaf(-2.0f, fb.y, cnf.y);
                INS2(bv0, bv1, bi0, bi1, s2, n);
                INS2(bv0, bv1, bi0, bi1, s3, n + 1);
                thrB = __half2half2(__float2half_rn(bv1));
            }
        }
        buf = (buf == 2) ? 0 : buf + 1;
        nbuf = (nbuf == 2) ? 0 : nbuf + 1;
    }

    /* ---- stash 8 candidates per token in smem (ring drained) ---- */
    CP_WAIT0();
    __syncthreads();
    int*   scand = (int*)smem;                  /* [128 tokens][8 cands] = 4KB */
    float* swsq  = (float*)(smem + 4096);
    int*   sflag = (int*)(smem + 4096 + 32);
    {
        int ta = warp * 16 + r, tb = ta + 8;
        scand[ta * 8 + cc * 2]     = ai0;
        scand[ta * 8 + cc * 2 + 1] = ai1;
        scand[tb * 8 + cc * 2]     = bi0;
        scand[tb * 8 + cc * 2 + 1] = bi1;
    }
    __syncthreads();

    /* ---- exact fp32 rescore of 8 candidates: group g=lane>>2 owns cand g,
            sub=lane&3 covers 32 dims ---- */
    const int g = lane >> 2;
    const int sub = lane & 3;
    float warp_sq = 0.0f;
    for (int j = 0; j < 16; j++) {
        const int tl = warp * 16 + j;
        const int t = m0 + tl;
        int cj = scand[tl * 8 + g];
        const float4* zt = (const float4*)(z + (size_t)t * DIM);
        const float4* cb = (const float4*)(g_codebook + (size_t)cj * DIM);
        float d = 0.0f;
#pragma unroll
        for (int k = 0; k < 8; k++) {
            float4 a = zt[sub + 4 * k];
            float4 b = cb[sub + 4 * k];
            d = fmaf(a.x, b.x, d);
            d = fmaf(a.y, b.y, d);
            d = fmaf(a.z, b.z, d);
            d = fmaf(a.w, b.w, d);
        }
        d += __shfl_xor_sync(0xffffffffu, d, 1);
        d += __shfl_xor_sync(0xffffffffu, d, 2);
        float bv = g_cnorm[cj] - 2.0f * d;
        int bidx = cj;
#pragma unroll
        for (int o = 4; o <= 16; o <<= 1) {
            float ov = __shfl_xor_sync(0xffffffffu, bv, o);
            int   oi = __shfl_xor_sync(0xffffffffu, bidx, o);
            if (ov < bv || (ov == bv && oi < bidx)) { bv = ov; bidx = oi; }
        }

        float4 zv = zt[lane];
        float4 c  = ((const float4*)(g_codebook + (size_t)bidx * DIM))[lane];
        float dx = c.x - zv.x, dy = c.y - zv.y, dz = c.z - zv.z, dw = c.w - zv.w;
        float4 o4;
        o4.x = zv.x + dx; o4.y = zv.y + dy; o4.z = zv.z + dz; o4.w = zv.w + dw;
        ((float4*)(out + (size_t)t * DIM))[lane] = o4;

        float sq = dx * dx + dy * dy + dz * dz + dw * dw;
#pragma unroll
        for (int o = 16; o > 0; o >>= 1) sq += __shfl_xor_sync(0xffffffffu, sq, o);
        warp_sq += sq;
        if (lane == 0) atomicAdd(&g_counts[bidx], 1);
    }
    if (lane == 0) swsq[warp] = warp_sq;
    __syncthreads();
    if (tid == 0) {
        double s = 0.0;
#pragma unroll
        for (int i = 0; i < 8; i++) s += (double)swsq[i];
        g_ssep[blockIdx.x] = s;
        __threadfence();
        unsigned int t = atomicAdd(&g_done, 1u);
        *sflag = (t == GRID_GEMM - 1) ? 1 : 0;
    }
    __syncthreads();

    /* ---- last CTA computes commit_loss + perplexity ---- */
    if (*sflag) {
        __threadfence();
        __shared__ double wd[8];
        __shared__ float wf[8];
        double sd = g_ssep[tid];
        float s = 0.0f;
        const float invT = 1.0f / (float)T_TOK;
        for (int i = tid; i < KC; i += 256) {
            float e = (float)g_counts[i] * invT;
            s += e * logf(e + 1e-8f);
        }
#pragma unroll
        for (int o = 16; o > 0; o >>= 1) {
            sd += __shfl_down_sync(0xffffffffu, sd, o);
            s  += __shfl_down_sync(0xffffffffu, s, o);
        }
        if (lane == 0) { wd[warp] = sd; wf[warp] = s; }
        __syncthreads();
        if (tid == 0) {
            double td = 0.0; float tf = 0.0f;
#pragma unroll
            for (int i = 0; i < 8; i++) { td += wd[i]; tf += wf[i]; }
            double mse = td / (double)((size_t)T_TOK * DIM);
            out[(size_t)T_TOK * DIM]     = (float)(1.25 * mse);
            out[(size_t)T_TOK * DIM + 1] = expf(-tf);
        }
    }
}

extern "C" void kernel_launch(void* const* d_in, const int* in_sizes, int n_in,
                              void* d_out, int out_size) {
    const float* z   = (const float*)d_in[0];
    const float* emb = (const float*)d_in[1];
    const float* pw  = (const float*)d_in[2];
    const float* pb  = (const float*)d_in[3];
    float* out = (float*)d_out;

    cudaFuncSetAttribute(k_proj, cudaFuncAttributeMaxDynamicSharedMemorySize, SMEM_PROJ);
    cudaFuncSetAttribute(k_gemm, cudaFuncAttributeMaxDynamicSharedMemorySize, SMEM_GEMM);

    k_proj<<<KC / 128, 256, SMEM_PROJ>>>(emb, pw, pb);
    k_gemm<<<GRID_GEMM, 256, SMEM_GEMM>>>(z, out);
}